// round 10
// baseline (speedup 1.0000x reference)
#include <cuda_runtime.h>
#include <cstdint>

// ---------------------------------------------------------------------------
// CrossWarpingModule: B=2, C=64, H=W=256 -> 4 parity sub-images of 128x128,
// 8-head axial attention (per-head channel dim = 1), flow, bilinear warp.
//
//   K1  k_qkv  : 1x1 convs -> Q, K, V. 384-thread blocks (Q/K/V role thirds,
//                8 accumulators each -> low regs), 3-deep cp.async pipeline.
//   K2  k_attn : MOMENT-BASED axial softmax (exp(qk) = sum q^n/n! k^n ->
//                29 per-line moments + deg-14 Horner per query). K,V staged
//                in smem (with transpose for dir=1); Q streamed from global.
//   K3  k_warp : bilinear border grid-sample + parity re-interleave.
// ---------------------------------------------------------------------------

#define PLANE 16384  // 128*128
typedef unsigned long long u64;
typedef unsigned int u32;

__device__ float g_Q [8][8][PLANE];
__device__ float g_K [8][8][PLANE];
__device__ float g_V [8][8][PLANE];
__device__ float g_flow[2][8][PLANE];  // dir0 = horizontal, dir1 = vertical

// ------------------------- packed f32x2 helpers ----------------------------
__device__ __forceinline__ u64 pk2f(float lo, float hi) {
    u64 r; asm("mov.b64 %0,{%1,%2};" : "=l"(r) : "f"(lo), "f"(hi)); return r;
}
__device__ __forceinline__ void upk2f(u64 v, float& lo, float& hi) {
    asm("mov.b64 {%0,%1},%2;" : "=f"(lo), "=f"(hi) : "l"(v));
}
__device__ __forceinline__ u64 fma2(u64 a, u64 b, u64 c) {
    u64 d; asm("fma.rn.f32x2 %0,%1,%2,%3;" : "=l"(d) : "l"(a), "l"(b), "l"(c)); return d;
}
__device__ __forceinline__ void cp16(u32 smem_dst, const void* gsrc) {
    asm volatile("cp.async.cg.shared.global [%0], [%1], 16;\n"
                 :: "r"(smem_dst), "l"(gsrc) : "memory");
}
__device__ __forceinline__ void cp_commit() {
    asm volatile("cp.async.commit_group;\n" ::: "memory");
}
template <int N> __device__ __forceinline__ void cp_wait() {
    asm volatile("cp.async.wait_group %0;\n" :: "n"(N) : "memory");
}

// ---------------------------------------------------------------------------
// K1: QKV projections via 3-stage cp.async pipeline, role-split warps.
// Block = one original row (b, y) = 128 pixel-pairs, 384 threads:
//   t in [0,128)   : Q accumulation for pair p=t   (from cur)
//   t in [128,256) : K accumulation for pair p=t-128 (from ref)
//   t in [256,384) : V accumulation for pair p=t-256 (from ref)
// Tiles: 8 channels x 256 floats of BOTH streams (16KB); threads t<256 copy
// 64B each (4 x cp.async 16B). 3 buffers in flight.
// ---------------------------------------------------------------------------
__global__ __launch_bounds__(384) void k_qkv(
    const float* __restrict__ cur, const float* __restrict__ ref,
    const float* __restrict__ Wq, const float* __restrict__ Wk,
    const float* __restrict__ Wv)
{
    __shared__ u64 sW[3][512];               // 12 KB packed weights
    __shared__ float sIn[3][2][8][256];      // [buf][stream][ch][x]  48 KB

    int t = threadIdx.x;
    for (int i = t; i < 512; i += 384) {
        float wq = Wq[i], wk = Wk[i], wv = Wv[i];
        sW[0][i] = pk2f(wq, wq);
        sW[1][i] = pk2f(wk, wk);
        sW[2][i] = pk2f(wv, wv);
    }

    int row = blockIdx.x;                    // 512 rows = 2(b) * 256(y)
    int b   = row >> 8;
    int y   = row & 255;

    // copy mapping (threads t < 256): stream, channel-in-tile, 64B slice
    int ls = t >> 7;                         // 0 = cur, 1 = ref (t<256)
    int lc = (t >> 4) & 7;
    int x0 = (t & 15) * 16;
    const float* g0 = (ls ? ref : cur)
        + ((size_t)b * 64 + lc) * 65536 + y * 256 + x0;
    u32 sdst = (u32)__cvta_generic_to_shared(&sIn[0][ls][lc][x0]);
    const u32 BUFSTRIDE = (u32)(2 * 8 * 256 * 4);
    bool docp = (t < 256);

    // prefetch tiles 0 and 1
    if (docp) {
#pragma unroll
        for (int k = 0; k < 4; ++k) cp16(sdst, g0 + k * 4), sdst += 16;
        sdst -= 64;
    }
    cp_commit();
    if (docp) {
        u32 d = sdst + BUFSTRIDE;
        const float* g = g0 + (size_t)8 * 65536;
#pragma unroll
        for (int k = 0; k < 4; ++k) cp16(d + k * 16, g + k * 4);
    }
    cp_commit();

    int role = t >> 7;                       // 0:Q 1:K 2:V
    int p    = t & 127;
    int strm = (role == 0) ? 0 : 1;
    u64 acc[8];
#pragma unroll
    for (int h = 0; h < 8; ++h) acc[h] = 0ull;

#pragma unroll
    for (int tile = 0; tile < 8; ++tile) {
        int buf = tile % 3;
        if (tile < 6) {
            if (docp) {
                u32 d = sdst + (u32)((tile + 2) % 3) * BUFSTRIDE;
                const float* g = g0 + (size_t)(tile + 2) * 8 * 65536;
#pragma unroll
                for (int k = 0; k < 4; ++k) cp16(d + k * 16, g + k * 4);
            }
            cp_commit();
            cp_wait<2>();
        } else if (tile == 6) {
            cp_wait<1>();
        } else {
            cp_wait<0>();
        }
        __syncthreads();

        int c0 = tile * 8;
        const u64* wrow = &sW[role][c0];
#pragma unroll
        for (int c = 0; c < 8; ++c) {
            float2 xv = *(const float2*)&sIn[buf][strm][c][2 * p];
            u64 x01 = pk2f(xv.x, xv.y);
#pragma unroll
            for (int h = 0; h < 8; ++h)
                acc[h] = fma2(wrow[h * 64 + c], x01, acc[h]);
        }
        __syncthreads();
    }

    // parity sub mapping: (dy,dx) -> s : (0,0)->0 (1,1)->1 (0,1)->2 (1,0)->3
    int dyp = y & 1, h2 = y >> 1;
    int s0  = dyp ? 3 : 0;                   // even-x pixel (lo lane)
    int s1  = dyp ? 1 : 2;                   // odd-x pixel (hi lane)
    int sb0 = s0 * 2 + b, sb1 = s1 * 2 + b;
    int off = h2 * 128 + p;

    float* dst = (role == 0) ? &g_Q[0][0][0]
               : (role == 1) ? &g_K[0][0][0] : &g_V[0][0][0];
#pragma unroll
    for (int h = 0; h < 8; ++h) {
        float lo, hi;
        upk2f(acc[h], lo, hi);
        dst[(sb0 * 8 + h) * PLANE + off] = lo;
        dst[(sb1 * 8 + h) * PLANE + off] = hi;
    }
}

// ---------------------------------------------------------------------------
// K2: moment-based axial attention. K,V staged in smem (transposed for
// dir=1); Q streamed from global per head. Block = (dir, sb, 4 lines),
// 128 threads, warp per line, 4 positions per thread.
// ---------------------------------------------------------------------------
#define NDEG 14

__global__ __launch_bounds__(128) void k_attn(
    const float* __restrict__ Wver, const float* __restrict__ Whor)
{
    __shared__ float sT[2][8][4][128];   // {K,V}, head, line-in-block, pos (32KB)

    int t    = threadIdx.x;
    int wid  = t >> 5;
    int lane = t & 31;
    int bid  = blockIdx.x;               // 512 = 2 dir * 8 sb * 32 groups
    int dir  = bid >> 8;
    int sb   = (bid >> 5) & 7;
    int lg   = bid & 31;
    int c0   = lg * 4;                   // first line of this block

    const float* kv_arr[2] = { &g_K[sb][0][0], &g_V[sb][0][0] };
    const float* qp = &g_Q[sb][0][0];

    if (dir == 0) {
        int off = (c0 + wid) * 128 + lane * 4;
#pragma unroll
        for (int a = 0; a < 2; ++a)
#pragma unroll
            for (int h = 0; h < 8; ++h) {
                float4 v = *(const float4*)(kv_arr[a] + h * PLANE + off);
                *(float4*)&sT[a][h][wid][lane * 4] = v;
            }
    } else {
        int off = t * 128 + c0;
#pragma unroll
        for (int a = 0; a < 2; ++a)
#pragma unroll
            for (int h = 0; h < 8; ++h) {
                float4 v = *(const float4*)(kv_arr[a] + h * PLANE + off);
                sT[a][h][0][t] = v.x;
                sT[a][h][1][t] = v.y;
                sT[a][h][2][t] = v.z;
                sT[a][h][3][t] = v.w;
            }
    }
    __syncthreads();

    const float* wdp = dir ? Wver : Whor;

    const float invf[NDEG + 1] = {
        1.0f, 1.0f, 0.5f, 1.0f / 6.0f, 1.0f / 24.0f, 1.0f / 120.0f,
        1.0f / 720.0f, 1.0f / 5040.0f, 1.0f / 40320.0f, 1.0f / 362880.0f,
        1.0f / 3628800.0f, 1.0f / 39916800.0f, 1.0f / 479001600.0f,
        1.0f / 6227020800.0f, 1.0f / 87178291200.0f };

    float fl0 = 0.f, fl1 = 0.f, fl2 = 0.f, fl3 = 0.f;

    // Q fetch helpers -------------------------------------------------------
    // dir0: q[(c0+wid)*128 + lane*4 .. +3]  (coalesced float4)
    // dir1: q[(lane*4+i)*128 + c0+wid]      (4 scalars, L2-resident)
    float4 q4;
    if (dir == 0)
        q4 = *(const float4*)(qp + (c0 + wid) * 128 + lane * 4);
    else {
        const float* qb = qp + (lane * 4) * 128 + c0 + wid;
        q4 = make_float4(qb[0], qb[128], qb[256], qb[384]);
    }

#pragma unroll 1
    for (int head = 0; head < 8; ++head) {
        float4 nq;
        if (head < 7) {
            const float* qn = qp + (head + 1) * PLANE;
            if (dir == 0)
                nq = *(const float4*)(qn + (c0 + wid) * 128 + lane * 4);
            else {
                const float* qb = qn + (lane * 4) * 128 + c0 + wid;
                nq = make_float4(qb[0], qb[128], qb[256], qb[384]);
            }
        }
        float wdh = wdp[head];
        float4 k4 = *(const float4*)&sT[0][head][wid][lane * 4];
        float4 v4 = *(const float4*)&sT[1][head][wid][lane * 4];

        float m[NDEG + 1];
        float mv[NDEG + 1];
#pragma unroll
        for (int n = 0; n <= NDEG; ++n) { m[n] = 0.f; mv[n] = 0.f; }

        {
            float kk, vv, tt;
#define ACCUM(KX, VX)                                        \
            kk = (KX); vv = (VX); tt = kk;                   \
            mv[0] += vv;                                     \
            _Pragma("unroll")                                \
            for (int n = 1; n <= NDEG; ++n) {                \
                m[n] += tt;                                  \
                mv[n] = fmaf(tt, vv, mv[n]);                 \
                tt *= kk;                                    \
            }
            ACCUM(k4.x, v4.x)
            ACCUM(k4.y, v4.y)
            ACCUM(k4.z, v4.z)
            ACCUM(k4.w, v4.w)
#undef ACCUM
        }

#pragma unroll
        for (int off = 16; off; off >>= 1) {
            mv[0] += __shfl_xor_sync(0xffffffffu, mv[0], off);
#pragma unroll
            for (int n = 1; n <= NDEG; ++n) {
                m[n]  += __shfl_xor_sync(0xffffffffu, m[n],  off);
                mv[n] += __shfl_xor_sync(0xffffffffu, mv[n], off);
            }
        }

        m[0] = 128.0f;
#pragma unroll
        for (int n = 2; n <= NDEG; ++n) {
            m[n]  *= invf[n];
            mv[n] *= invf[n];
        }

#define EVAL(QX, FL)                                          \
        {                                                     \
            float q = (QX);                                   \
            float den = m[NDEG], num = mv[NDEG];              \
            _Pragma("unroll")                                 \
            for (int n = NDEG - 1; n >= 0; --n) {             \
                den = fmaf(den, q, m[n]);                     \
                num = fmaf(num, q, mv[n]);                    \
            }                                                 \
            FL = fmaf(wdh, __fdividef(num, den), FL);         \
        }
        EVAL(q4.x, fl0)
        EVAL(q4.y, fl1)
        EVAL(q4.z, fl2)
        EVAL(q4.w, fl3)
#undef EVAL
        q4 = nq;
    }

    int base = (c0 + wid) * 128 + lane * 4;
    *(float4*)&g_flow[dir][sb][base] = make_float4(fl0, fl1, fl2, fl3);
}

// ---------------------------------------------------------------------------
// K3: bilinear border grid-sample + parity re-interleave.
// 4x channel-split; gathers batched 8 channels (32 loads in flight).
// ---------------------------------------------------------------------------
__global__ __launch_bounds__(256) void k_warp(
    const float* __restrict__ ref, float* __restrict__ out)
{
    int idx = blockIdx.x * 256 + threadIdx.x;   // 524288
    int pix = idx & 16383;
    int cid = (idx >> 14) & 3;                  // channel chunk 0..3
    int sb  = idx >> 16;                        // 0..7
    int h2  = pix >> 7, w2 = pix & 127;
    int s   = sb >> 1, b = sb & 1;
    int dy  = (s == 1 || s == 3) ? 1 : 0;
    int dx  = (s == 1 || s == 2) ? 1 : 0;

    float fx = g_flow[0][sb][(h2 << 7) + w2];
    float fy = g_flow[1][sb][(w2 << 7) + h2];
    float ix = (float)w2 + fx;
    float iy = (float)h2 + fy;
    float x0f = floorf(ix), y0f = floorf(iy);
    float wx = ix - x0f, wy = iy - y0f;
    int x0 = (int)x0f, y0 = (int)y0f;
    int x0c = min(max(x0, 0), 127), x1c = min(max(x0 + 1, 0), 127);
    int y0c = min(max(y0, 0), 127), y1c = min(max(y0 + 1, 0), 127);

    int X0 = 2 * x0c + dx, X1 = 2 * x1c + dx;
    int Y0 = 2 * y0c + dy, Y1 = 2 * y1c + dy;
    int o00 = Y0 * 256 + X0, o01 = Y0 * 256 + X1;
    int o10 = Y1 * 256 + X0, o11 = Y1 * 256 + X1;

    float w11 = wx * wy;
    float w01 = wx - w11;
    float w10 = wy - w11;
    float w00 = 1.f - wx - wy + w11;

    int c0 = cid * 16;
    const float* rp = ref + ((size_t)b * 64 + c0) * 65536;
    float*       op = out + ((size_t)b * 64 + c0) * 65536
                          + (2 * h2 + dy) * 256 + (2 * w2 + dx);

#pragma unroll
    for (int cc = 0; cc < 16; cc += 8) {
        float t00[8], t01[8], t10[8], t11[8];
#pragma unroll
        for (int c = 0; c < 8; ++c) {
            const float* p = rp + (size_t)(cc + c) * 65536;
            t00[c] = p[o00];
            t01[c] = p[o01];
            t10[c] = p[o10];
            t11[c] = p[o11];
        }
#pragma unroll
        for (int c = 0; c < 8; ++c) {
            float v = w00 * t00[c];
            v = fmaf(w01, t01[c], v);
            v = fmaf(w10, t10[c], v);
            v = fmaf(w11, t11[c], v);
            op[(size_t)(cc + c) * 65536] = v;
        }
    }
}

// ---------------------------------------------------------------------------
extern "C" void kernel_launch(void* const* d_in, const int* in_sizes, int n_in,
                              void* d_out, int out_size)
{
    const float* cur  = (const float*)d_in[0];
    const float* ref  = (const float*)d_in[1];
    const float* Wq   = (const float*)d_in[2];
    const float* Wk   = (const float*)d_in[3];
    const float* Wv   = (const float*)d_in[4];
    const float* Wver = (const float*)d_in[5];
    const float* Whor = (const float*)d_in[6];
    float* out = (float*)d_out;

    k_qkv<<<512, 384>>>(cur, ref, Wq, Wk, Wv);
    k_attn<<<512, 128>>>(Wver, Whor);
    k_warp<<<2048, 256>>>(ref, out);
}

// round 11
// speedup vs baseline: 1.6426x; 1.6426x over previous
#include <cuda_runtime.h>
#include <cstdint>

// ---------------------------------------------------------------------------
// CrossWarpingModule: B=2, C=64, H=W=256 -> 4 parity sub-images of 128x128,
// 8-head axial attention (per-head channel dim = 1), flow, bilinear warp.
//
//   K1  k_qkv  : 1x1 convs -> Q, K, V. cp.async double-buffered smem staging
//                (round-9 known-good version).
//   K2  k_attn : MOMENT-BASED axial softmax (exp(qk) = sum q^n/n! k^n ->
//                per-line moments + deg-12 Horner per query). 256-thread
//                blocks: warp = (line, head-half) for 2x warp parallelism;
//                in-kernel transpose for the vertical direction.
//   K3  k_warp : bilinear border grid-sample + parity re-interleave.
// ---------------------------------------------------------------------------

#define PLANE 16384  // 128*128
typedef unsigned long long u64;
typedef unsigned int u32;

__device__ float g_Q [8][8][PLANE];
__device__ float g_K [8][8][PLANE];
__device__ float g_V [8][8][PLANE];
__device__ float g_flow[2][8][PLANE];  // dir0 = horizontal, dir1 = vertical

// ------------------------- packed f32x2 helpers ----------------------------
__device__ __forceinline__ u64 pk2f(float lo, float hi) {
    u64 r; asm("mov.b64 %0,{%1,%2};" : "=l"(r) : "f"(lo), "f"(hi)); return r;
}
__device__ __forceinline__ void upk2f(u64 v, float& lo, float& hi) {
    asm("mov.b64 {%0,%1},%2;" : "=f"(lo), "=f"(hi) : "l"(v));
}
__device__ __forceinline__ u64 fma2(u64 a, u64 b, u64 c) {
    u64 d; asm("fma.rn.f32x2 %0,%1,%2,%3;" : "=l"(d) : "l"(a), "l"(b), "l"(c)); return d;
}
__device__ __forceinline__ void cp16(u32 smem_dst, const void* gsrc) {
    asm volatile("cp.async.cg.shared.global [%0], [%1], 16;\n"
                 :: "r"(smem_dst), "l"(gsrc) : "memory");
}
__device__ __forceinline__ void cp_commit() {
    asm volatile("cp.async.commit_group;\n" ::: "memory");
}
template <int N> __device__ __forceinline__ void cp_wait() {
    asm volatile("cp.async.wait_group %0;\n" :: "n"(N) : "memory");
}

// ---------------------------------------------------------------------------
// K1: QKV projections via cp.async-staged tiles (round-9 version).
// Block = one original row (b, y) = 128 pixel-pairs. 8-channel double-buffered
// tiles of cur AND ref staged to smem; each thread copies 64B/tile.
// Threads t<128: Q for pair p=t (cur); t>=128: K,V for pair p=t-128 (ref).
// ---------------------------------------------------------------------------
__global__ __launch_bounds__(256) void k_qkv(
    const float* __restrict__ cur, const float* __restrict__ ref,
    const float* __restrict__ Wq, const float* __restrict__ Wk,
    const float* __restrict__ Wv)
{
    __shared__ u64 sW[3][512];               // 12 KB packed weights
    __shared__ float sIn[2][2][8][256];      // [buf][stream][ch][x]  32 KB

    int t = threadIdx.x;
    for (int i = t; i < 512; i += 256) {
        float wq = Wq[i], wk = Wk[i], wv = Wv[i];
        sW[0][i] = pk2f(wq, wq);
        sW[1][i] = pk2f(wk, wk);
        sW[2][i] = pk2f(wv, wv);
    }

    int row = blockIdx.x;                    // 512 rows = 2(b) * 256(y)
    int b   = row >> 8;
    int y   = row & 255;

    int ls = t >> 7;                         // 0 = cur, 1 = ref
    int lc = (t >> 4) & 7;                   // channel within 8-ch tile
    int x0 = (t & 15) * 16;                  // float offset within row
    const float* g0 = (ls ? ref : cur)
        + ((size_t)b * 64 + lc) * 65536 + y * 256 + x0;
    u32 sdst = (u32)__cvta_generic_to_shared(&sIn[0][ls][lc][x0]);
    const u32 BUFSTRIDE = (u32)(2 * 8 * 256 * 4);

#pragma unroll
    for (int k = 0; k < 4; ++k)
        cp16(sdst + k * 16, g0 + k * 4);
    cp_commit();

    int half = t >> 7;                       // 0: Q-role, 1: KV-role
    int p    = t & 127;                      // pixel pair
    u64 acc0[8], acc1[8];
#pragma unroll
    for (int h = 0; h < 8; ++h) { acc0[h] = 0ull; acc1[h] = 0ull; }

#pragma unroll
    for (int tile = 0; tile < 8; ++tile) {
        int buf = tile & 1;
        if (tile < 7) {
            u32 d = sdst + (u32)((tile + 1) & 1) * BUFSTRIDE;
            const float* g = g0 + (size_t)(tile + 1) * 8 * 65536;
#pragma unroll
            for (int k = 0; k < 4; ++k)
                cp16(d + k * 16, g + k * 4);
            cp_commit();
            cp_wait<1>();
        } else {
            cp_wait<0>();
        }
        __syncthreads();

        int c0 = tile * 8;
        if (half == 0) {
#pragma unroll
            for (int c = 0; c < 8; ++c) {
                float2 xv = *(const float2*)&sIn[buf][0][c][2 * p];
                u64 x01 = pk2f(xv.x, xv.y);
#pragma unroll
                for (int h = 0; h < 8; ++h)
                    acc0[h] = fma2(sW[0][h * 64 + c0 + c], x01, acc0[h]);
            }
        } else {
#pragma unroll
            for (int c = 0; c < 8; ++c) {
                float2 xv = *(const float2*)&sIn[buf][1][c][2 * p];
                u64 x01 = pk2f(xv.x, xv.y);
#pragma unroll
                for (int h = 0; h < 8; ++h) {
                    acc0[h] = fma2(sW[1][h * 64 + c0 + c], x01, acc0[h]);
                    acc1[h] = fma2(sW[2][h * 64 + c0 + c], x01, acc1[h]);
                }
            }
        }
        __syncthreads();
    }

    // parity sub mapping: (dy,dx) -> s : (0,0)->0 (1,1)->1 (0,1)->2 (1,0)->3
    int dyp = y & 1, h2 = y >> 1;
    int s0  = dyp ? 3 : 0;                   // even-x pixel (lo lane)
    int s1  = dyp ? 1 : 2;                   // odd-x pixel (hi lane)
    int sb0 = s0 * 2 + b, sb1 = s1 * 2 + b;
    int off = h2 * 128 + p;

    if (half == 0) {
#pragma unroll
        for (int h = 0; h < 8; ++h) {
            float lo, hi;
            upk2f(acc0[h], lo, hi);
            g_Q[sb0][h][off] = lo; g_Q[sb1][h][off] = hi;
        }
    } else {
#pragma unroll
        for (int h = 0; h < 8; ++h) {
            float lo, hi;
            upk2f(acc0[h], lo, hi);
            g_K[sb0][h][off] = lo; g_K[sb1][h][off] = hi;
            upk2f(acc1[h], lo, hi);
            g_V[sb0][h][off] = lo; g_V[sb1][h][off] = hi;
        }
    }
}

// ---------------------------------------------------------------------------
// K2: moment-based axial attention, head-parallel.
// Block = (dir, sb, 4 lines); 256 threads = 8 warps; warp = (line, head-half).
// Q/K/V for all 8 heads of the block's 4 lines staged in smem (transposed
// staging for dir=1). Each warp builds deg-12 moments for its line over its
// 4 heads; the two half-warps combine partial flows through smem.
// ---------------------------------------------------------------------------
#define NDEG 12

__global__ __launch_bounds__(256) void k_attn(
    const float* __restrict__ Wver, const float* __restrict__ Whor)
{
    __shared__ float sT[3][8][4][128];   // arr, head, line-in-block, pos (48KB)
    __shared__ float sP[4][128];         // partial flow (heads 4-7)
    __shared__ float swd[8];

    int t    = threadIdx.x;
    int wid  = t >> 5;
    int lane = t & 31;
    int bid  = blockIdx.x;               // 512 = 2 dir * 8 sb * 32 groups
    int dir  = bid >> 8;
    int sb   = (bid >> 5) & 7;
    int lg   = bid & 31;
    int c0   = lg * 4;                   // first line of this block

    const float* base_arr[3] = { &g_Q[sb][0][0], &g_K[sb][0][0], &g_V[sb][0][0] };

    // ---- stage into smem: 3072 float4s, 12 per thread ----
    if (dir == 0) {
#pragma unroll
        for (int j = 0; j < 12; ++j) {
            int id = j * 256 + t;
            int a  = id >> 10;
            int r  = id & 1023;
            int h  = r >> 7;
            int lw = (r >> 5) & 3;
            int l4 = r & 31;
            float4 v = *(const float4*)(base_arr[a] + h * PLANE
                                        + (c0 + lw) * 128 + l4 * 4);
            *(float4*)&sT[a][h][lw][l4 * 4] = v;
        }
    } else {
#pragma unroll
        for (int j = 0; j < 12; ++j) {
            int id = j * 256 + t;
            int a  = id >> 10;
            int h  = (id >> 7) & 7;
            int r  = id & 127;
            float4 v = *(const float4*)(base_arr[a] + h * PLANE + r * 128 + c0);
            sT[a][h][0][r] = v.x;
            sT[a][h][1][r] = v.y;
            sT[a][h][2][r] = v.z;
            sT[a][h][3][r] = v.w;
        }
    }
    if (t < 8) swd[t] = dir ? Wver[t] : Whor[t];
    __syncthreads();

    const float invf[NDEG + 1] = {
        1.0f, 1.0f, 0.5f, 1.0f / 6.0f, 1.0f / 24.0f, 1.0f / 120.0f,
        1.0f / 720.0f, 1.0f / 5040.0f, 1.0f / 40320.0f, 1.0f / 362880.0f,
        1.0f / 3628800.0f, 1.0f / 39916800.0f, 1.0f / 479001600.0f };

    int line = wid >> 1;                 // 0..3
    int hh   = wid & 1;                  // head half: 0 -> heads 0-3, 1 -> 4-7

    float fl0 = 0.f, fl1 = 0.f, fl2 = 0.f, fl3 = 0.f;

#pragma unroll 1
    for (int hi = 0; hi < 4; ++hi) {
        int head  = hh * 4 + hi;
        float wdh = swd[head];
        float4 q4 = *(const float4*)&sT[0][head][line][lane * 4];
        float4 k4 = *(const float4*)&sT[1][head][line][lane * 4];
        float4 v4 = *(const float4*)&sT[2][head][line][lane * 4];

        float m[NDEG + 1];
        float mv[NDEG + 1];
#pragma unroll
        for (int n = 0; n <= NDEG; ++n) { m[n] = 0.f; mv[n] = 0.f; }

        {
            float kk, vv, tt;
#define ACCUM(KX, VX)                                        \
            kk = (KX); vv = (VX); tt = kk;                   \
            mv[0] += vv;                                     \
            _Pragma("unroll")                                \
            for (int n = 1; n <= NDEG; ++n) {                \
                m[n] += tt;                                  \
                mv[n] = fmaf(tt, vv, mv[n]);                 \
                tt *= kk;                                    \
            }
            ACCUM(k4.x, v4.x)
            ACCUM(k4.y, v4.y)
            ACCUM(k4.z, v4.z)
            ACCUM(k4.w, v4.w)
#undef ACCUM
        }

#pragma unroll
        for (int off = 16; off; off >>= 1) {
            mv[0] += __shfl_xor_sync(0xffffffffu, mv[0], off);
#pragma unroll
            for (int n = 1; n <= NDEG; ++n) {
                m[n]  += __shfl_xor_sync(0xffffffffu, m[n],  off);
                mv[n] += __shfl_xor_sync(0xffffffffu, mv[n], off);
            }
        }

        m[0] = 128.0f;
#pragma unroll
        for (int n = 2; n <= NDEG; ++n) {
            m[n]  *= invf[n];
            mv[n] *= invf[n];
        }

#define EVAL(QX, FL)                                          \
        {                                                     \
            float q = (QX);                                   \
            float den = m[NDEG], num = mv[NDEG];              \
            _Pragma("unroll")                                 \
            for (int n = NDEG - 1; n >= 0; --n) {             \
                den = fmaf(den, q, m[n]);                     \
                num = fmaf(num, q, mv[n]);                    \
            }                                                 \
            FL = fmaf(wdh, __fdividef(num, den), FL);         \
        }
        EVAL(q4.x, fl0)
        EVAL(q4.y, fl1)
        EVAL(q4.z, fl2)
        EVAL(q4.w, fl3)
#undef EVAL
    }

    // combine the two head halves
    if (hh == 1)
        *(float4*)&sP[line][lane * 4] = make_float4(fl0, fl1, fl2, fl3);
    __syncthreads();
    if (hh == 0) {
        float4 p4 = *(const float4*)&sP[line][lane * 4];
        int base = (c0 + line) * 128 + lane * 4;
        *(float4*)&g_flow[dir][sb][base] =
            make_float4(fl0 + p4.x, fl1 + p4.y, fl2 + p4.z, fl3 + p4.w);
    }
}

// ---------------------------------------------------------------------------
// K3: bilinear border grid-sample + parity re-interleave.
// 4x channel-split; gathers batched 8 channels (32 loads in flight).
// ---------------------------------------------------------------------------
__global__ __launch_bounds__(256) void k_warp(
    const float* __restrict__ ref, float* __restrict__ out)
{
    int idx = blockIdx.x * 256 + threadIdx.x;   // 524288
    int pix = idx & 16383;
    int cid = (idx >> 14) & 3;                  // channel chunk 0..3
    int sb  = idx >> 16;                        // 0..7
    int h2  = pix >> 7, w2 = pix & 127;
    int s   = sb >> 1, b = sb & 1;
    int dy  = (s == 1 || s == 3) ? 1 : 0;
    int dx  = (s == 1 || s == 2) ? 1 : 0;

    float fx = g_flow[0][sb][(h2 << 7) + w2];
    float fy = g_flow[1][sb][(w2 << 7) + h2];
    float ix = (float)w2 + fx;
    float iy = (float)h2 + fy;
    float x0f = floorf(ix), y0f = floorf(iy);
    float wx = ix - x0f, wy = iy - y0f;
    int x0 = (int)x0f, y0 = (int)y0f;
    int x0c = min(max(x0, 0), 127), x1c = min(max(x0 + 1, 0), 127);
    int y0c = min(max(y0, 0), 127), y1c = min(max(y0 + 1, 0), 127);

    int X0 = 2 * x0c + dx, X1 = 2 * x1c + dx;
    int Y0 = 2 * y0c + dy, Y1 = 2 * y1c + dy;
    int o00 = Y0 * 256 + X0, o01 = Y0 * 256 + X1;
    int o10 = Y1 * 256 + X0, o11 = Y1 * 256 + X1;

    float w11 = wx * wy;
    float w01 = wx - w11;
    float w10 = wy - w11;
    float w00 = 1.f - wx - wy + w11;

    int c0 = cid * 16;
    const float* rp = ref + ((size_t)b * 64 + c0) * 65536;
    float*       op = out + ((size_t)b * 64 + c0) * 65536
                          + (2 * h2 + dy) * 256 + (2 * w2 + dx);

#pragma unroll
    for (int cc = 0; cc < 16; cc += 8) {
        float t00[8], t01[8], t10[8], t11[8];
#pragma unroll
        for (int c = 0; c < 8; ++c) {
            const float* p = rp + (size_t)(cc + c) * 65536;
            t00[c] = p[o00];
            t01[c] = p[o01];
            t10[c] = p[o10];
            t11[c] = p[o11];
        }
#pragma unroll
        for (int c = 0; c < 8; ++c) {
            float v = w00 * t00[c];
            v = fmaf(w01, t01[c], v);
            v = fmaf(w10, t10[c], v);
            v = fmaf(w11, t11[c], v);
            op[(size_t)(cc + c) * 65536] = v;
        }
    }
}

// ---------------------------------------------------------------------------
extern "C" void kernel_launch(void* const* d_in, const int* in_sizes, int n_in,
                              void* d_out, int out_size)
{
    const float* cur  = (const float*)d_in[0];
    const float* ref  = (const float*)d_in[1];
    const float* Wq   = (const float*)d_in[2];
    const float* Wk   = (const float*)d_in[3];
    const float* Wv   = (const float*)d_in[4];
    const float* Wver = (const float*)d_in[5];
    const float* Whor = (const float*)d_in[6];
    float* out = (float*)d_out;

    k_qkv<<<512, 256>>>(cur, ref, Wq, Wk, Wv);
    k_attn<<<512, 256>>>(Wver, Whor);
    k_warp<<<2048, 256>>>(ref, out);
}

// round 12
// speedup vs baseline: 1.7422x; 1.0607x over previous
#include <cuda_runtime.h>
#include <cstdint>

// ---------------------------------------------------------------------------
// CrossWarpingModule: B=2, C=64, H=W=256 -> 4 parity sub-images of 128x128,
// 8-head axial attention (per-head channel dim = 1), flow, bilinear warp.
//
//   K1  k_qkv  : 1x1 convs -> Q, K, V. cp.async double-buffered smem staging
//                (round-9 known-good version).
//   K2  k_attn : MOMENT-BASED axial softmax. Phase 1: octet-parallel moment
//                build (8 lanes per (head,line) task -> 3-step butterfly
//                instead of 5 -> 6.7x fewer SHFLs), moments parked in smem.
//                Phase 2: per-query deg-12 Horner eval (r11 layout).
//   K3  k_warp : bilinear border grid-sample + parity re-interleave.
// ---------------------------------------------------------------------------

#define PLANE 16384  // 128*128
typedef unsigned long long u64;
typedef unsigned int u32;

__device__ float g_Q [8][8][PLANE];
__device__ float g_K [8][8][PLANE];
__device__ float g_V [8][8][PLANE];
__device__ float g_flow[2][8][PLANE];  // dir0 = horizontal, dir1 = vertical

// ------------------------- packed f32x2 helpers ----------------------------
__device__ __forceinline__ u64 pk2f(float lo, float hi) {
    u64 r; asm("mov.b64 %0,{%1,%2};" : "=l"(r) : "f"(lo), "f"(hi)); return r;
}
__device__ __forceinline__ void upk2f(u64 v, float& lo, float& hi) {
    asm("mov.b64 {%0,%1},%2;" : "=f"(lo), "=f"(hi) : "l"(v));
}
__device__ __forceinline__ u64 fma2(u64 a, u64 b, u64 c) {
    u64 d; asm("fma.rn.f32x2 %0,%1,%2,%3;" : "=l"(d) : "l"(a), "l"(b), "l"(c)); return d;
}
__device__ __forceinline__ void cp16(u32 smem_dst, const void* gsrc) {
    asm volatile("cp.async.cg.shared.global [%0], [%1], 16;\n"
                 :: "r"(smem_dst), "l"(gsrc) : "memory");
}
__device__ __forceinline__ void cp_commit() {
    asm volatile("cp.async.commit_group;\n" ::: "memory");
}
template <int N> __device__ __forceinline__ void cp_wait() {
    asm volatile("cp.async.wait_group %0;\n" :: "n"(N) : "memory");
}

// ---------------------------------------------------------------------------
// K1: QKV projections via cp.async-staged tiles (round-9 version, frozen).
// ---------------------------------------------------------------------------
__global__ __launch_bounds__(256) void k_qkv(
    const float* __restrict__ cur, const float* __restrict__ ref,
    const float* __restrict__ Wq, const float* __restrict__ Wk,
    const float* __restrict__ Wv)
{
    __shared__ u64 sW[3][512];               // 12 KB packed weights
    __shared__ float sIn[2][2][8][256];      // [buf][stream][ch][x]  32 KB

    int t = threadIdx.x;
    for (int i = t; i < 512; i += 256) {
        float wq = Wq[i], wk = Wk[i], wv = Wv[i];
        sW[0][i] = pk2f(wq, wq);
        sW[1][i] = pk2f(wk, wk);
        sW[2][i] = pk2f(wv, wv);
    }

    int row = blockIdx.x;                    // 512 rows = 2(b) * 256(y)
    int b   = row >> 8;
    int y   = row & 255;

    int ls = t >> 7;                         // 0 = cur, 1 = ref
    int lc = (t >> 4) & 7;                   // channel within 8-ch tile
    int x0 = (t & 15) * 16;                  // float offset within row
    const float* g0 = (ls ? ref : cur)
        + ((size_t)b * 64 + lc) * 65536 + y * 256 + x0;
    u32 sdst = (u32)__cvta_generic_to_shared(&sIn[0][ls][lc][x0]);
    const u32 BUFSTRIDE = (u32)(2 * 8 * 256 * 4);

#pragma unroll
    for (int k = 0; k < 4; ++k)
        cp16(sdst + k * 16, g0 + k * 4);
    cp_commit();

    int half = t >> 7;                       // 0: Q-role, 1: KV-role
    int p    = t & 127;                      // pixel pair
    u64 acc0[8], acc1[8];
#pragma unroll
    for (int h = 0; h < 8; ++h) { acc0[h] = 0ull; acc1[h] = 0ull; }

#pragma unroll
    for (int tile = 0; tile < 8; ++tile) {
        int buf = tile & 1;
        if (tile < 7) {
            u32 d = sdst + (u32)((tile + 1) & 1) * BUFSTRIDE;
            const float* g = g0 + (size_t)(tile + 1) * 8 * 65536;
#pragma unroll
            for (int k = 0; k < 4; ++k)
                cp16(d + k * 16, g + k * 4);
            cp_commit();
            cp_wait<1>();
        } else {
            cp_wait<0>();
        }
        __syncthreads();

        int c0 = tile * 8;
        if (half == 0) {
#pragma unroll
            for (int c = 0; c < 8; ++c) {
                float2 xv = *(const float2*)&sIn[buf][0][c][2 * p];
                u64 x01 = pk2f(xv.x, xv.y);
#pragma unroll
                for (int h = 0; h < 8; ++h)
                    acc0[h] = fma2(sW[0][h * 64 + c0 + c], x01, acc0[h]);
            }
        } else {
#pragma unroll
            for (int c = 0; c < 8; ++c) {
                float2 xv = *(const float2*)&sIn[buf][1][c][2 * p];
                u64 x01 = pk2f(xv.x, xv.y);
#pragma unroll
                for (int h = 0; h < 8; ++h) {
                    acc0[h] = fma2(sW[1][h * 64 + c0 + c], x01, acc0[h]);
                    acc1[h] = fma2(sW[2][h * 64 + c0 + c], x01, acc1[h]);
                }
            }
        }
        __syncthreads();
    }

    // parity sub mapping: (dy,dx) -> s : (0,0)->0 (1,1)->1 (0,1)->2 (1,0)->3
    int dyp = y & 1, h2 = y >> 1;
    int s0  = dyp ? 3 : 0;                   // even-x pixel (lo lane)
    int s1  = dyp ? 1 : 2;                   // odd-x pixel (hi lane)
    int sb0 = s0 * 2 + b, sb1 = s1 * 2 + b;
    int off = h2 * 128 + p;

    if (half == 0) {
#pragma unroll
        for (int h = 0; h < 8; ++h) {
            float lo, hi;
            upk2f(acc0[h], lo, hi);
            g_Q[sb0][h][off] = lo; g_Q[sb1][h][off] = hi;
        }
    } else {
#pragma unroll
        for (int h = 0; h < 8; ++h) {
            float lo, hi;
            upk2f(acc0[h], lo, hi);
            g_K[sb0][h][off] = lo; g_K[sb1][h][off] = hi;
            upk2f(acc1[h], lo, hi);
            g_V[sb0][h][off] = lo; g_V[sb1][h][off] = hi;
        }
    }
}

// ---------------------------------------------------------------------------
// K2: moment-based axial attention, octet-parallel moments.
// Block = (dir, sb, 4 lines); 256 threads.
// Phase 1: 32 tasks = 8 heads x 4 lines; each task = one 8-lane octet.
//   Lane covers 16 positions (4 float4s at sl*4 + r*32), builds deg-12
//   moments locally, butterflies over xor {4,2,1} (3 steps), octet leader
//   folds 1/n! and writes 25 floats to sM.
// Phase 2: warp = (line, head-half); moments re-read as LDS broadcasts,
//   deg-12 Horner per query position, halves combined via sP.
// ---------------------------------------------------------------------------
#define NDEG 12

__global__ __launch_bounds__(256) void k_attn(
    const float* __restrict__ Wver, const float* __restrict__ Whor)
{
    __shared__ float sT[3][8][4][132];   // arr, head, line, pos (padded) ~50KB
    __shared__ float sM[32][26];         // folded moments per task
    __shared__ float sP[4][128];         // partial flow (heads 4-7)
    __shared__ float swd[8];

    int t    = threadIdx.x;
    int wid  = t >> 5;
    int lane = t & 31;
    int bid  = blockIdx.x;               // 512 = 2 dir * 8 sb * 32 groups
    int dir  = bid >> 8;
    int sb   = (bid >> 5) & 7;
    int lg   = bid & 31;
    int c0   = lg * 4;                   // first line of this block

    const float* base_arr[3] = { &g_Q[sb][0][0], &g_K[sb][0][0], &g_V[sb][0][0] };

    // ---- stage into smem: 3072 float4s, 12 per thread ----
    if (dir == 0) {
#pragma unroll
        for (int j = 0; j < 12; ++j) {
            int id = j * 256 + t;
            int a  = id >> 10;
            int r  = id & 1023;
            int h  = r >> 7;
            int lw = (r >> 5) & 3;
            int l4 = r & 31;
            float4 v = *(const float4*)(base_arr[a] + h * PLANE
                                        + (c0 + lw) * 128 + l4 * 4);
            *(float4*)&sT[a][h][lw][l4 * 4] = v;
        }
    } else {
#pragma unroll
        for (int j = 0; j < 12; ++j) {
            int id = j * 256 + t;
            int a  = id >> 10;
            int h  = (id >> 7) & 7;
            int r  = id & 127;
            float4 v = *(const float4*)(base_arr[a] + h * PLANE + r * 128 + c0);
            sT[a][h][0][r] = v.x;
            sT[a][h][1][r] = v.y;
            sT[a][h][2][r] = v.z;
            sT[a][h][3][r] = v.w;
        }
    }
    if (t < 8) swd[t] = dir ? Wver[t] : Whor[t];
    __syncthreads();

    const float invf[NDEG + 1] = {
        1.0f, 1.0f, 0.5f, 1.0f / 6.0f, 1.0f / 24.0f, 1.0f / 120.0f,
        1.0f / 720.0f, 1.0f / 5040.0f, 1.0f / 40320.0f, 1.0f / 362880.0f,
        1.0f / 3628800.0f, 1.0f / 39916800.0f, 1.0f / 479001600.0f };

    // ================= Phase 1: octet moment build =================
    {
        int tq   = lane >> 3;            // task within warp (0..3)
        int sl   = lane & 7;             // sub-lane within octet
        int task = wid * 4 + tq;         // 0..31
        int head = task & 7;
        int line = task >> 3;

        float m[NDEG + 1], mv[NDEG + 1];
#pragma unroll
        for (int n = 0; n <= NDEG; ++n) { m[n] = 0.f; mv[n] = 0.f; }

        {
            float kk, vv, tt;
#define ACCUM(KX, VX)                                        \
            kk = (KX); vv = (VX); tt = kk;                   \
            mv[0] += vv;                                     \
            _Pragma("unroll")                                \
            for (int n = 1; n <= NDEG; ++n) {                \
                m[n] += tt;                                  \
                mv[n] = fmaf(tt, vv, mv[n]);                 \
                tt *= kk;                                    \
            }
#pragma unroll
            for (int r = 0; r < 4; ++r) {
                int p = sl * 4 + r * 32;
                float4 k4 = *(const float4*)&sT[1][head][line][p];
                float4 v4 = *(const float4*)&sT[2][head][line][p];
                ACCUM(k4.x, v4.x)
                ACCUM(k4.y, v4.y)
                ACCUM(k4.z, v4.z)
                ACCUM(k4.w, v4.w)
            }
#undef ACCUM
        }

        // 3-step butterfly within the octet
#pragma unroll
        for (int off = 4; off; off >>= 1) {
            mv[0] += __shfl_xor_sync(0xffffffffu, mv[0], off);
#pragma unroll
            for (int n = 1; n <= NDEG; ++n) {
                m[n]  += __shfl_xor_sync(0xffffffffu, m[n],  off);
                mv[n] += __shfl_xor_sync(0xffffffffu, mv[n], off);
            }
        }

        if (sl == 0) {
            float* Mo = sM[task];
            Mo[0] = m[1];
#pragma unroll
            for (int n = 2; n <= NDEG; ++n) Mo[n - 1] = m[n] * invf[n];
            Mo[12] = mv[0];
            Mo[13] = mv[1];
#pragma unroll
            for (int n = 2; n <= NDEG; ++n) Mo[12 + n] = mv[n] * invf[n];
        }
    }
    __syncthreads();

    // ================= Phase 2: Horner evaluation =================
    int line = wid >> 1;                 // 0..3
    int hh   = wid & 1;                  // head half

    float fl0 = 0.f, fl1 = 0.f, fl2 = 0.f, fl3 = 0.f;

#pragma unroll 1
    for (int hi = 0; hi < 4; ++hi) {
        int head  = hh * 4 + hi;
        float wdh = swd[head];
        const float* Mi = sM[(line << 3) | head];

        float m[NDEG + 1], mv[NDEG + 1];
        m[0] = 128.0f;
        m[1] = Mi[0];
#pragma unroll
        for (int n = 2; n <= NDEG; ++n) m[n] = Mi[n - 1];
        mv[0] = Mi[12];
        mv[1] = Mi[13];
#pragma unroll
        for (int n = 2; n <= NDEG; ++n) mv[n] = Mi[12 + n];

        float4 q4 = *(const float4*)&sT[0][head][line][lane * 4];

#define EVAL(QX, FL)                                          \
        {                                                     \
            float q = (QX);                                   \
            float den = m[NDEG], num = mv[NDEG];              \
            _Pragma("unroll")                                 \
            for (int n = NDEG - 1; n >= 0; --n) {             \
                den = fmaf(den, q, m[n]);                     \
                num = fmaf(num, q, mv[n]);                    \
            }                                                 \
            FL = fmaf(wdh, __fdividef(num, den), FL);         \
        }
        EVAL(q4.x, fl0)
        EVAL(q4.y, fl1)
        EVAL(q4.z, fl2)
        EVAL(q4.w, fl3)
#undef EVAL
    }

    // combine the two head halves
    if (hh == 1)
        *(float4*)&sP[line][lane * 4] = make_float4(fl0, fl1, fl2, fl3);
    __syncthreads();
    if (hh == 0) {
        float4 p4 = *(const float4*)&sP[line][lane * 4];
        int base = (c0 + line) * 128 + lane * 4;
        *(float4*)&g_flow[dir][sb][base] =
            make_float4(fl0 + p4.x, fl1 + p4.y, fl2 + p4.z, fl3 + p4.w);
    }
}

// ---------------------------------------------------------------------------
// K3: bilinear border grid-sample + parity re-interleave.
// 4x channel-split; gathers batched 8 channels (32 loads in flight).
// ---------------------------------------------------------------------------
__global__ __launch_bounds__(256) void k_warp(
    const float* __restrict__ ref, float* __restrict__ out)
{
    int idx = blockIdx.x * 256 + threadIdx.x;   // 524288
    int pix = idx & 16383;
    int cid = (idx >> 14) & 3;                  // channel chunk 0..3
    int sb  = idx >> 16;                        // 0..7
    int h2  = pix >> 7, w2 = pix & 127;
    int s   = sb >> 1, b = sb & 1;
    int dy  = (s == 1 || s == 3) ? 1 : 0;
    int dx  = (s == 1 || s == 2) ? 1 : 0;

    float fx = g_flow[0][sb][(h2 << 7) + w2];
    float fy = g_flow[1][sb][(w2 << 7) + h2];
    float ix = (float)w2 + fx;
    float iy = (float)h2 + fy;
    float x0f = floorf(ix), y0f = floorf(iy);
    float wx = ix - x0f, wy = iy - y0f;
    int x0 = (int)x0f, y0 = (int)y0f;
    int x0c = min(max(x0, 0), 127), x1c = min(max(x0 + 1, 0), 127);
    int y0c = min(max(y0, 0), 127), y1c = min(max(y0 + 1, 0), 127);

    int X0 = 2 * x0c + dx, X1 = 2 * x1c + dx;
    int Y0 = 2 * y0c + dy, Y1 = 2 * y1c + dy;
    int o00 = Y0 * 256 + X0, o01 = Y0 * 256 + X1;
    int o10 = Y1 * 256 + X0, o11 = Y1 * 256 + X1;

    float w11 = wx * wy;
    float w01 = wx - w11;
    float w10 = wy - w11;
    float w00 = 1.f - wx - wy + w11;

    int c0 = cid * 16;
    const float* rp = ref + ((size_t)b * 64 + c0) * 65536;
    float*       op = out + ((size_t)b * 64 + c0) * 65536
                          + (2 * h2 + dy) * 256 + (2 * w2 + dx);

#pragma unroll
    for (int cc = 0; cc < 16; cc += 8) {
        float t00[8], t01[8], t10[8], t11[8];
#pragma unroll
        for (int c = 0; c < 8; ++c) {
            const float* p = rp + (size_t)(cc + c) * 65536;
            t00[c] = p[o00];
            t01[c] = p[o01];
            t10[c] = p[o10];
            t11[c] = p[o11];
        }
#pragma unroll
        for (int c = 0; c < 8; ++c) {
            float v = w00 * t00[c];
            v = fmaf(w01, t01[c], v);
            v = fmaf(w10, t10[c], v);
            v = fmaf(w11, t11[c], v);
            op[(size_t)(cc + c) * 65536] = v;
        }
    }
}

// ---------------------------------------------------------------------------
extern "C" void kernel_launch(void* const* d_in, const int* in_sizes, int n_in,
                              void* d_out, int out_size)
{
    const float* cur  = (const float*)d_in[0];
    const float* ref  = (const float*)d_in[1];
    const float* Wq   = (const float*)d_in[2];
    const float* Wk   = (const float*)d_in[3];
    const float* Wv   = (const float*)d_in[4];
    const float* Wver = (const float*)d_in[5];
    const float* Whor = (const float*)d_in[6];
    float* out = (float*)d_out;

    k_qkv<<<512, 256>>>(cur, ref, Wq, Wk, Wv);
    k_attn<<<512, 256>>>(Wver, Whor);
    k_warp<<<2048, 256>>>(ref, out);
}